// round 4
// baseline (speedup 1.0000x reference)
#include <cuda_runtime.h>

#define KS 7
#define PAD 3
#define TILE_W 128
#define TILE_H 64
#define SW 136                     // staged row: gx in [bx-4, bx+132)
#define SH 70
#define ROW_CHUNKS 34              // 34 x 16B per row
#define TCHUNKS (SH * ROW_CHUNKS)  // 2380
#define NTILES 2048                // 8x * 16y * 16b
#define GRID_CTAS 304              // 2 per SM
#define BUF_FLOATS (SH * SW)       // 9520
#define SMEM_BYTES (2 * BUF_FLOATS * 4 + 49 * 8)

typedef unsigned long long u64;

__device__ __forceinline__ u64 pk2(float lo, float hi) {
    u64 r; asm("mov.b64 %0, {%1,%2};" : "=l"(r) : "f"(lo), "f"(hi)); return r;
}
__device__ __forceinline__ void fma2(u64& d, u64 a, u64 b) {
    asm("fma.rn.f32x2 %0, %1, %2, %0;" : "+l"(d) : "l"(a), "l"(b));
}
__device__ __forceinline__ void unpk2(u64 v, float& lo, float& hi) {
    asm("mov.b64 {%0,%1}, %2;" : "=f"(lo), "=f"(hi) : "l"(v));
}
__device__ __forceinline__ void cpa16(unsigned dst, const float* src, unsigned nbytes) {
    asm volatile("cp.async.ca.shared.global [%0], [%1], 16, %2;"
                 :: "r"(dst), "l"(src), "r"(nbytes) : "memory");
}

extern __shared__ float smem[];

__device__ __forceinline__ void stage_tile(const float* __restrict__ img, int t,
                                           unsigned sbuf, int tid) {
    int b   = t >> 7;
    int rem = t & 127;
    int by  = (rem >> 3) * TILE_H;
    int bx  = (rem & 7) * TILE_W;
    const float* src = img + ((size_t)b * 3 + 2) * (size_t)(1024 * 1024); // last channel

    #pragma unroll
    for (int k = 0; k < 10; k++) {
        int i = tid + k * 256;
        if (i < TCHUNKS) {
            int r  = i / ROW_CHUNKS;
            int c  = i - r * ROW_CHUNKS;
            int gy = by + r - PAD;
            int gx = bx - 4 + c * 4;
            unsigned ok = ((unsigned)gy < 1024u && (unsigned)gx < 1024u) ? 16u : 0u;
            const float* p = src + (size_t)(gy & 1023) * 1024 + (gx & 1023);
            cpa16(sbuf + (unsigned)(r * SW + c * 4) * 4u, p, ok);
        }
    }
    asm volatile("cp.async.commit_group;" ::: "memory");
}

__global__ __launch_bounds__(256, 2)
void Conv_8443905704574_kernel(const float* __restrict__ img,
                               const float* __restrict__ ker,
                               float* __restrict__ out) {
    const int tid = threadIdx.x;
    float* buf0 = smem;
    float* buf1 = smem + BUF_FLOATS;
    u64*   kw2  = (u64*)(smem + 2 * BUF_FLOATS);

    if (tid < 49) {
        float w = ker[tid];
        kw2[tid] = pk2(w, w);
    }

    unsigned sbase;
    asm("{ .reg .u64 t; cvta.to.shared.u64 t, %1; cvt.u32.u64 %0, t; }"
        : "=r"(sbase) : "l"(smem));
    const unsigned sb0 = sbase;
    const unsigned sb1 = sbase + BUF_FLOATS * 4;

    const int tx   = tid & 15;    // 16 threads x 8 px = 128 cols
    const int ty   = tid >> 4;    // 0..15
    const int row0 = ty * 4;      // 4 output rows per thread

    int t = blockIdx.x;
    if (t < NTILES) stage_tile(img, t, sb0, tid);
    int cur = 0;

    while (t < NTILES) {
        int nxt = t + GRID_CTAS;
        if (nxt < NTILES) {
            stage_tile(img, nxt, cur ? sb0 : sb1, tid);
            asm volatile("cp.async.wait_group 1;" ::: "memory");
        } else {
            asm volatile("cp.async.wait_group 0;" ::: "memory");
        }
        __syncthreads();

        const float* B = cur ? buf1 : buf0;

        // acc[o][p] = output pixels (2p, 2p+1) of output row (row0+o)
        u64 acc[4][4];
        #pragma unroll
        for (int o = 0; o < 4; o++)
            #pragma unroll
            for (int p = 0; p < 4; p++) acc[o][p] = 0ull;

        // Sliding 10-row window; each input row loaded once, feeds up to 4 output rows.
        #pragma unroll
        for (int r = 0; r < 10; r++) {
            const float* row = B + (row0 + r) * SW + tx * 8;
            float4 A0 = *(const float4*)(row);
            float4 A1 = *(const float4*)(row + 4);
            float4 A2 = *(const float4*)(row + 8);
            float4 A3 = *(const float4*)(row + 12);
            float v[16] = {A0.x, A0.y, A0.z, A0.w, A1.x, A1.y, A1.z, A1.w,
                           A2.x, A2.y, A2.z, A2.w, A3.x, A3.y, A3.z, A3.w};
            // P[i] = (v[i], v[i+1]); pixel-pair (j,j+1) with tap kx uses P[j+1+kx]
            u64 P[14];
            #pragma unroll
            for (int i = 1; i <= 13; i++) P[i] = pk2(v[i], v[i + 1]);

            #pragma unroll
            for (int o = 0; o < 4; o++) {
                const int ky = r - o;
                if (ky >= 0 && ky < KS) {
                    #pragma unroll
                    for (int kx = 0; kx < KS; kx++) {
                        u64 ww = kw2[ky * 7 + kx];   // broadcast; CSE across o
                        fma2(acc[o][0], P[1 + kx], ww);
                        fma2(acc[o][1], P[3 + kx], ww);
                        fma2(acc[o][2], P[5 + kx], ww);
                        fma2(acc[o][3], P[7 + kx], ww);
                    }
                }
            }
        }

        // store: 8 px per row -> 2 STG.128 per row per channel, streaming hint
        int b   = t >> 7;
        int rem = t & 127;
        int by  = (rem >> 3) * TILE_H;
        int bx  = (rem & 7) * TILE_W;
        int ox  = bx + tx * 8;
        size_t obase = (size_t)b * 3 * 1024 * 1024;
        #pragma unroll
        for (int o = 0; o < 4; o++) {
            float4 lo4, hi4;
            unpk2(acc[o][0], lo4.x, lo4.y);
            unpk2(acc[o][1], lo4.z, lo4.w);
            unpk2(acc[o][2], hi4.x, hi4.y);
            unpk2(acc[o][3], hi4.z, hi4.w);
            size_t off = obase + (size_t)(by + row0 + o) * 1024 + ox;
            #pragma unroll
            for (int c = 0; c < 3; c++) {
                __stcs((float4*)(out + off + (size_t)c * 1024 * 1024),     lo4);
                __stcs((float4*)(out + off + (size_t)c * 1024 * 1024 + 4), hi4);
            }
        }

        __syncthreads();   // buffer reuse protection
        cur ^= 1;
        t = nxt;
    }
}

extern "C" void kernel_launch(void* const* d_in, const int* in_sizes, int n_in,
                              void* d_out, int out_size) {
    const float* img = (const float*)d_in[0];
    const float* ker = (const float*)d_in[1];
    float* out = (float*)d_out;

    cudaFuncSetAttribute(Conv_8443905704574_kernel,
                         cudaFuncAttributeMaxDynamicSharedMemorySize, SMEM_BYTES);
    Conv_8443905704574_kernel<<<GRID_CTAS, 256, SMEM_BYTES>>>(img, ker, out);
}